// round 3
// baseline (speedup 1.0000x reference)
#include <cuda_runtime.h>
#include <cstdint>

#define BN   128
#define LN   256
#define HN   256
#define ENM  30
#define TT   501
#define H3   768

// ---- static device scratch (no allocation) ----
__device__ float g_Wcat[512 * 1024];                   // [c][n] n: 0..255 proj, 256..1023 G
__device__ float g_projT[(size_t)BN * HN * LN];        // [b][h][l]
__device__ float g_G[(size_t)BN * LN * H3];            // [b][l][k]
__device__ float g_P[BN * LN * 4];                     // [b][l][j]
__device__ float g_Wh2hT[HN * HN];                     // [j][i]
__device__ float g_WhhT[HN * H3];                      // [j][k]
__device__ float g_WgenT[HN * 32];                     // [j][m]
__device__ float g_WlgHT[HN * 4];                      // [j][m]
__device__ float g_OH[ENM * H3];                       // [e][k]
__device__ float g_S[4];
__device__ float g_hid4[(size_t)BN * TT * 4];

__device__ __forceinline__ float tanh_acc(float x) {
    float a = __expf(2.0f * fabsf(x));
    return copysignf(1.0f - 2.0f / (a + 1.0f), x);
}
__device__ __forceinline__ float sigm(float x) { return 1.0f / (1.0f + __expf(-x)); }

// ---- K0: pack weights ----
__global__ void k0_prep(const float* __restrict__ W_i2h, const float* __restrict__ W_h2h,
                        const float* __restrict__ W_ih,  const float* __restrict__ W_hh,
                        const float* __restrict__ W_gen, const float* __restrict__ W_lg)
{
    const int NW = 512 * 1024;
    const int O1 = NW, O2 = O1 + 256 * 256, O3 = O2 + 256 * 768, O4 = O3 + 256 * 32;
    const int O5 = O4 + 256 * 4, O6 = O5 + 30 * 768, TOT = O6 + 4;
    for (int i = blockIdx.x * blockDim.x + threadIdx.x; i < TOT; i += gridDim.x * blockDim.x) {
        if (i < NW) {
            int c = i >> 10, n = i & 1023;
            g_Wcat[i] = (n < 256) ? W_i2h[n * 512 + c] : W_ih[(n - 256) * 542 + c];
        } else if (i < O2) {
            int e = i - O1, j = e >> 8, ii = e & 255;
            g_Wh2hT[e] = W_h2h[ii * 256 + j];
        } else if (i < O3) {
            int e = i - O2, j = e / 768, k = e % 768;
            g_WhhT[e] = W_hh[k * 256 + j];
        } else if (i < O4) {
            int e = i - O3, j = e >> 5, m = e & 31;
            g_WgenT[e] = (m < 30) ? W_gen[m * 256 + j] : 0.0f;
        } else if (i < O5) {
            int e = i - O4, j = e >> 2, m = e & 3;
            g_WlgHT[e] = W_lg[m * 768 + j];
        } else if (i < O6) {
            int e = i - O5, eo = e / 768, k = e % 768;
            g_OH[e] = W_ih[k * 542 + 512 + eo];
        } else {
            int j = i - O6; float s = 0.0f;
            for (int c = 0; c < 512; c++) s += W_lg[j * 768 + 256 + c];
            g_S[j] = s;
        }
    }
}

// ---- KP: P[b,l,j] = fea[b,l,:]·W_lg[j,256:768] ----
__global__ __launch_bounds__(256) void kP(const float* __restrict__ fea, const float* __restrict__ W_lg)
{
    __shared__ float Wl[4 * 512];
    const int b = blockIdx.y, tid = threadIdx.x, lane = tid & 31, w = tid >> 5;
    for (int i = tid; i < 2048; i += 256) Wl[i] = W_lg[(i >> 9) * 768 + 256 + (i & 511)];
    __syncthreads();
    int l = blockIdx.x * 8 + w;
    float a0 = 0, a1 = 0, a2 = 0, a3 = 0;
    const float* fp = fea + ((size_t)(b * 256 + l)) * 512;
    for (int i = 0; i < 16; i++) {
        int c = lane + 32 * i; float f = fp[c];
        a0 = fmaf(f, Wl[c], a0); a1 = fmaf(f, Wl[512 + c], a1);
        a2 = fmaf(f, Wl[1024 + c], a2); a3 = fmaf(f, Wl[1536 + c], a3);
    }
    for (int o = 16; o; o >>= 1) {
        a0 += __shfl_xor_sync(~0u, a0, o); a1 += __shfl_xor_sync(~0u, a1, o);
        a2 += __shfl_xor_sync(~0u, a2, o); a3 += __shfl_xor_sync(~0u, a3, o);
    }
    if (lane < 4) {
        float v = (lane == 0) ? a0 : (lane == 1) ? a1 : (lane == 2) ? a2 : a3;
        g_P[(size_t)(b * 256 + l) * 4 + lane] = v;
    }
}

// ---- K1: [32768 x 512] @ [512 x 1024] -> projT / G ----
__global__ __launch_bounds__(256) void k1_gemm(const float* __restrict__ fea)
{
    __shared__ float As[16 * 128];  // [kk][m]
    __shared__ float Bs[16 * 128];  // [kk][n]
    const int m0 = blockIdx.y * 128, n0 = blockIdx.x * 128;
    const int tid = threadIdx.x, ty = tid >> 4, tx = tid & 15;
    float acc[8][8];
#pragma unroll
    for (int i = 0; i < 8; i++)
#pragma unroll
        for (int j = 0; j < 8; j++) acc[i][j] = 0.0f;

    for (int k0 = 0; k0 < 512; k0 += 16) {
#pragma unroll
        for (int s = 0; s < 2; s++) {
            int idx = tid + s * 256;
            int row = idx >> 2, c4 = idx & 3;
            float4 v = *(const float4*)(fea + (size_t)(m0 + row) * 512 + k0 + c4 * 4);
            As[(c4 * 4 + 0) * 128 + row] = v.x; As[(c4 * 4 + 1) * 128 + row] = v.y;
            As[(c4 * 4 + 2) * 128 + row] = v.z; As[(c4 * 4 + 3) * 128 + row] = v.w;
        }
#pragma unroll
        for (int s = 0; s < 2; s++) {
            int idx = tid + s * 256;
            int kk = idx >> 5, n4 = idx & 31;
            *(float4*)(Bs + kk * 128 + n4 * 4) =
                *(const float4*)(g_Wcat + (size_t)(k0 + kk) * 1024 + n0 + n4 * 4);
        }
        __syncthreads();
#pragma unroll
        for (int kk = 0; kk < 16; kk++) {
            float4 a0 = *(float4*)(As + kk * 128 + ty * 8);
            float4 a1 = *(float4*)(As + kk * 128 + ty * 8 + 4);
            float4 b0 = *(float4*)(Bs + kk * 128 + tx * 8);
            float4 b1 = *(float4*)(Bs + kk * 128 + tx * 8 + 4);
            float av[8] = {a0.x, a0.y, a0.z, a0.w, a1.x, a1.y, a1.z, a1.w};
            float bv[8] = {b0.x, b0.y, b0.z, b0.w, b1.x, b1.y, b1.z, b1.w};
#pragma unroll
            for (int i = 0; i < 8; i++)
#pragma unroll
                for (int j = 0; j < 8; j++) acc[i][j] = fmaf(av[i], bv[j], acc[i][j]);
        }
        __syncthreads();
    }
    const int b = m0 >> 8, l0 = m0 & 255;
    if (n0 < 256) {
#pragma unroll
        for (int i = 0; i < 8; i++)
#pragma unroll
            for (int j = 0; j < 8; j++)
                g_projT[((size_t)b * 256 + n0 + tx * 8 + j) * 256 + l0 + ty * 8 + i] = acc[i][j];
    } else {
#pragma unroll
        for (int i = 0; i < 8; i++) {
            float* gp = g_G + (size_t)(b * 256 + l0 + ty * 8 + i) * 768 + (n0 - 256) + tx * 8;
            *(float4*)gp = make_float4(acc[i][0], acc[i][1], acc[i][2], acc[i][3]);
            *(float4*)(gp + 4) = make_float4(acc[i][4], acc[i][5], acc[i][6], acc[i][7]);
        }
    }
}

// ---- K2: 501-step recurrence, one CTA per batch row ----
__global__ __launch_bounds__(1024, 1) void k2_loop(
    const float* __restrict__ b_h2h, const float* __restrict__ b_ih,
    const float* __restrict__ b_hh,  const float* __restrict__ w_score,
    const float* __restrict__ b_gen, float* __restrict__ probs_out)
{
    const int b = blockIdx.x, tid = threadIdx.x;
    __shared__ float h_s[256], q_s[256], e_s[256], gh_s[768], gi_s[768];
    __shared__ float part[1090];
    __shared__ float ws_s[256], bh2h_s[256], bih_s[768], bhh_s[768], bgen_s[32];
    __shared__ int elem_sh;

    if (tid < 256) { h_s[tid] = 0.0f; ws_s[tid] = w_score[tid]; bh2h_s[tid] = b_h2h[tid]; }
    if (tid < 768) { bih_s[tid] = b_ih[tid]; bhh_s[tid] = b_hh[tid]; }
    if (tid < 32)  bgen_s[tid] = (tid < 30) ? b_gen[tid] : 0.0f;
    if (tid == 0)  elem_sh = 0;
    __syncthreads();

    const float* projb = g_projT + (size_t)b * 256 * 256;
    const float* Gb    = g_G + (size_t)b * 256 * 768;

    for (int t = 0; t < TT; t++) {
        const int elem = elem_sh;
        // A: q (tid<256), gh (tid>=256)
        if (tid < 256) {
            const float* w = g_Wh2hT + tid;
            float a0 = 0, a1 = 0, a2 = 0, a3 = 0;
            for (int j = 0; j < 256; j += 4) {
                a0 = fmaf(w[(j + 0) * 256], h_s[j + 0], a0);
                a1 = fmaf(w[(j + 1) * 256], h_s[j + 1], a1);
                a2 = fmaf(w[(j + 2) * 256], h_s[j + 2], a2);
                a3 = fmaf(w[(j + 3) * 256], h_s[j + 3], a3);
            }
            q_s[tid] = a0 + a1 + a2 + a3 + bh2h_s[tid];
        } else {
            const int k = tid - 256;
            const float* w = g_WhhT + k;
            float a0 = 0, a1 = 0, a2 = 0, a3 = 0;
            for (int j = 0; j < 256; j += 4) {
                a0 = fmaf(w[(j + 0) * 768], h_s[j + 0], a0);
                a1 = fmaf(w[(j + 1) * 768], h_s[j + 1], a1);
                a2 = fmaf(w[(j + 2) * 768], h_s[j + 2], a2);
                a3 = fmaf(w[(j + 3) * 768], h_s[j + 3], a3);
            }
            gh_s[k] = a0 + a1 + a2 + a3 + bhh_s[k];
        }
        __syncthreads();
        // B: e[l] = sum_h ws[h]*tanh(projT[h][l]+q[h]), 4-way h split
        {
            const int l = tid & 255, c = tid >> 8;
            const float* pp = projb + (size_t)(c * 64) * 256 + l;
            float p = 0.0f;
#pragma unroll 4
            for (int hh = 0; hh < 64; hh++) {
                int h = c * 64 + hh;
                p = fmaf(ws_s[h], tanh_acc(pp[(size_t)hh * 256] + q_s[h]), p);
            }
            part[tid] = p;
        }
        __syncthreads();
        if (tid < 256) e_s[tid] = part[tid] + part[tid + 256] + part[tid + 512] + part[tid + 768];
        __syncthreads();
        // softmax(e)
        if (tid < 256) {
            float v = e_s[tid];
            for (int o = 16; o; o >>= 1) v = fmaxf(v, __shfl_xor_sync(~0u, v, o));
            if ((tid & 31) == 0) part[tid >> 5] = v;
        }
        __syncthreads();
        if (tid == 0) {
            float v = part[0];
            for (int w = 1; w < 8; w++) v = fmaxf(v, part[w]);
            part[32] = v;
        }
        __syncthreads();
        if (tid < 256) {
            float a = __expf(e_s[tid] - part[32]);
            e_s[tid] = a;
            for (int o = 16; o; o >>= 1) a += __shfl_xor_sync(~0u, a, o);
            if ((tid & 31) == 0) part[8 + (tid >> 5)] = a;
        }
        __syncthreads();
        if (tid == 0) {
            float v = 0.0f;
            for (int w = 0; w < 8; w++) v += part[8 + w];
            part[33] = 1.0f / v;
        }
        __syncthreads();
        if (tid < 256) e_s[tid] *= part[33];
        __syncthreads();
        // C: gi[k] = alpha·G[:,k] + b_ih[k] + OH[elem][k]
        if (tid < 768) {
            const float* gp = Gb + tid;
            float a0 = 0, a1 = 0, a2 = 0, a3 = 0;
            for (int l = 0; l < 256; l += 4) {
                a0 = fmaf(gp[(size_t)(l + 0) * 768], e_s[l + 0], a0);
                a1 = fmaf(gp[(size_t)(l + 1) * 768], e_s[l + 1], a1);
                a2 = fmaf(gp[(size_t)(l + 2) * 768], e_s[l + 2], a2);
                a3 = fmaf(gp[(size_t)(l + 3) * 768], e_s[l + 3], a3);
            }
            gi_s[tid] = a0 + a1 + a2 + a3 + bih_s[tid] + g_OH[elem * 768 + tid];
        }
        __syncthreads();
        // D: GRU combine
        if (tid < 256) {
            float r = sigm(gi_s[tid] + gh_s[tid]);
            float z = sigm(gi_s[256 + tid] + gh_s[256 + tid]);
            float n = tanh_acc(gi_s[512 + tid] + r * gh_s[512 + tid]);
            h_s[tid] = (1.0f - z) * n + z * h_s[tid];
        }
        __syncthreads();
        // E: logits -> probs + argmax
        if (tid < 256) {
            const int m = tid & 31, j0 = (tid >> 5) * 32;
            const float* wg = g_WgenT + j0 * 32 + m;
            float p = 0.0f;
#pragma unroll 8
            for (int jj = 0; jj < 32; jj++) p = fmaf(wg[jj * 32], h_s[j0 + jj], p);
            part[tid] = p;
        }
        __syncthreads();
        if (tid < 32) {
            float s = bgen_s[tid];
            for (int g = 0; g < 8; g++) s += part[tid + g * 32];
            float v = (tid < 30) ? s : -1e30f;
            float bv = v; int bi = tid;
            for (int o = 16; o; o >>= 1) {
                float ov = __shfl_down_sync(~0u, bv, o);
                int   oi = __shfl_down_sync(~0u, bi, o);
                if (ov > bv || (ov == bv && oi < bi)) { bv = ov; bi = oi; }
            }
            bv = __shfl_sync(~0u, bv, 0); bi = __shfl_sync(~0u, bi, 0);
            float ex = (tid < 30) ? __expf(v - bv) : 0.0f;
            float sm = ex;
            for (int o = 16; o; o >>= 1) sm += __shfl_xor_sync(~0u, sm, o);
            if (tid < 30) probs_out[((size_t)b * TT + t) * 30 + tid] = ex / sm;
            if (tid == 0) elem_sh = bi;
        }
        __syncthreads();
        // F: hid4[b,t,:] = W_locgen[:, :256] @ h_new
        {
            const int j = tid >> 2, m = tid & 3;
            float v = g_WlgHT[tid] * h_s[j];
            v += __shfl_xor_sync(~0u, v, 16);
            v += __shfl_xor_sync(~0u, v, 8);
            v += __shfl_xor_sync(~0u, v, 4);
            if ((tid & 31) < 4) part[(tid >> 5) * 4 + m] = v;
        }
        __syncthreads();
        if (tid < 4) {
            float s = 0.0f;
            for (int w = 0; w < 32; w++) s += part[w * 4 + tid];
            g_hid4[((size_t)b * TT + t) * 4 + tid] = s;
        }
        __syncthreads();
    }
}

// ---- K3: loc_preds ----
__global__ __launch_bounds__(256) void k3_loc(
    const float* __restrict__ Wlt, const float* __restrict__ blt,
    const float* __restrict__ blg, float* __restrict__ loc_out)
{
    __shared__ float Ps[1024];
    const int b = blockIdx.y, tid = threadIdx.x, lane = tid & 31, w = tid >> 5;
    for (int i = tid; i < 1024; i += 256) Ps[i] = g_P[(size_t)b * 1024 + i];
    __syncthreads();
    int t = blockIdx.x * 8 + w;
    if (t >= TT) return;
    float a0 = 0, a1 = 0, a2 = 0, a3 = 0;
    const float* wp = Wlt + (size_t)t * 256;
    for (int i = 0; i < 8; i++) {
        int l = lane + 32 * i;
        float wv = wp[l];
        float4 p = *(float4*)(Ps + l * 4);
        a0 = fmaf(wv, p.x, a0); a1 = fmaf(wv, p.y, a1);
        a2 = fmaf(wv, p.z, a2); a3 = fmaf(wv, p.w, a3);
    }
    for (int o = 16; o; o >>= 1) {
        a0 += __shfl_xor_sync(~0u, a0, o); a1 += __shfl_xor_sync(~0u, a1, o);
        a2 += __shfl_xor_sync(~0u, a2, o); a3 += __shfl_xor_sync(~0u, a3, o);
    }
    if (lane < 4) {
        float v = (lane == 0) ? a0 : (lane == 1) ? a1 : (lane == 2) ? a2 : a3;
        v += blt[t] * g_S[lane] + blg[lane] + g_hid4[((size_t)b * TT + t) * 4 + lane];
        loc_out[((size_t)b * TT + t) * 4 + lane] = sigm(v);
    }
}

extern "C" void kernel_launch(void* const* d_in, const int* in_sizes, int n_in,
                              void* d_out, int out_size)
{
    const float* fea     = (const float*)d_in[0];
    const float* W_i2h   = (const float*)d_in[1];
    const float* W_h2h   = (const float*)d_in[2];
    const float* b_h2h   = (const float*)d_in[3];
    const float* w_score = (const float*)d_in[4];
    const float* W_ih    = (const float*)d_in[5];
    const float* W_hh    = (const float*)d_in[6];
    const float* b_ih    = (const float*)d_in[7];
    const float* b_hh    = (const float*)d_in[8];
    const float* W_gen   = (const float*)d_in[9];
    const float* b_gen   = (const float*)d_in[10];
    const float* Wlt     = (const float*)d_in[11];
    const float* blt     = (const float*)d_in[12];
    const float* W_lg    = (const float*)d_in[13];
    const float* blg     = (const float*)d_in[14];

    float* out = (float*)d_out;
    float* probs = out;                                  // [128,501,30]
    float* loc   = out + (size_t)BN * TT * ENM;          // [128,501,4]

    k0_prep<<<256, 256>>>(W_i2h, W_h2h, W_ih, W_hh, W_gen, W_lg);
    kP<<<dim3(32, 128), 256>>>(fea, W_lg);
    k1_gemm<<<dim3(8, 256), 256>>>(fea);
    k2_loop<<<128, 1024>>>(b_h2h, b_ih, b_hh, w_score, b_gen, probs);
    k3_loc<<<dim3(63, 128), 256>>>(Wlt, blt, blg, loc);
}

// round 5
// speedup vs baseline: 1.0431x; 1.0431x over previous
#include <cuda_runtime.h>
#include <cstdint>

#define BN   128
#define LN   256
#define HN   256
#define ENM  30
#define TT   501
#define H3   768

// ---- static device scratch (no allocation) ----
__device__ __align__(16) float g_WcombT[256 * 1024];            // [j][o] o<256: W_h2h col, else W_hh
__device__ __align__(16) float g_WihcT[512 * H3];               // [c][k]
__device__ __align__(16) float g_Wcat1[512 * 256];              // [c][n] for proj GEMM
__device__ __align__(16) float g_projT[(size_t)BN * HN * LN];   // [b][h][l]
__device__ __align__(16) float g_P[BN * LN * 4];
__device__ __align__(16) float g_WgenT[HN * 32];
__device__ __align__(16) float g_WlgHT[HN * 4];
__device__ __align__(16) float g_OH[ENM * H3];
__device__ float g_S[4];
__device__ float g_hid4[(size_t)BN * TT * 4];

__device__ __forceinline__ float tanhfast(float x) {
    // tanh(x) = sign(x) * (1 - 2/(exp(2|x|)+1)); ex2/rcp approx ~1e-6 abs err
    float e, r;
    asm("ex2.approx.f32 %0, %1;" : "=f"(e) : "f"(fabsf(x) * 2.8853900817779268f));
    asm("rcp.approx.f32 %0, %1;" : "=f"(r) : "f"(e + 1.0f));
    return copysignf(1.0f - 2.0f * r, x);
}
__device__ __forceinline__ float sigm(float x) { return 1.0f / (1.0f + __expf(-x)); }

// ---- K0: pack weights ----
__global__ void k0_prep(const float* __restrict__ W_i2h, const float* __restrict__ W_h2h,
                        const float* __restrict__ W_ih,  const float* __restrict__ W_hh,
                        const float* __restrict__ W_gen, const float* __restrict__ W_lg)
{
    const int O1 = 256 * 1024;           // WcombT
    const int O2 = O1 + 512 * 768;       // WihcT
    const int O3 = O2 + 512 * 256;       // Wcat1
    const int O4 = O3 + 256 * 32;        // WgenT
    const int O5 = O4 + 256 * 4;         // WlgHT
    const int O6 = O5 + 30 * 768;        // OH
    const int TOT = O6 + 4;
    for (int i = blockIdx.x * blockDim.x + threadIdx.x; i < TOT; i += gridDim.x * blockDim.x) {
        if (i < O1) {
            int j = i >> 10, o = i & 1023;
            g_WcombT[i] = (o < 256) ? W_h2h[o * 256 + j] : W_hh[(o - 256) * 256 + j];
        } else if (i < O2) {
            int e = i - O1, c = e / 768, k = e % 768;
            g_WihcT[e] = W_ih[k * 542 + c];
        } else if (i < O3) {
            int e = i - O2, c = e >> 8, n = e & 255;
            g_Wcat1[e] = W_i2h[n * 512 + c];
        } else if (i < O4) {
            int e = i - O3, j = e >> 5, m = e & 31;
            g_WgenT[e] = (m < 30) ? W_gen[m * 256 + j] : 0.0f;
        } else if (i < O5) {
            int e = i - O4, j = e >> 2, m = e & 3;
            g_WlgHT[e] = W_lg[m * 768 + j];
        } else if (i < O6) {
            int e = i - O5, eo = e / 768, k = e % 768;
            g_OH[e] = W_ih[k * 542 + 512 + eo];
        } else {
            int j = i - O6; float s = 0.0f;
            for (int c = 0; c < 512; c++) s += W_lg[j * 768 + 256 + c];
            g_S[j] = s;
        }
    }
}

// ---- KP: P[b,l,j] = fea[b,l,:]·W_lg[j,256:768] ----
__global__ __launch_bounds__(256) void kP(const float* __restrict__ fea, const float* __restrict__ W_lg)
{
    __shared__ float Wl[4 * 512];
    const int b = blockIdx.y, tid = threadIdx.x, lane = tid & 31, w = tid >> 5;
    for (int i = tid; i < 2048; i += 256) Wl[i] = W_lg[(i >> 9) * 768 + 256 + (i & 511)];
    __syncthreads();
    int l = blockIdx.x * 8 + w;
    float a0 = 0, a1 = 0, a2 = 0, a3 = 0;
    const float* fp = fea + ((size_t)(b * 256 + l)) * 512;
    for (int i = 0; i < 16; i++) {
        int c = lane + 32 * i; float f = fp[c];
        a0 = fmaf(f, Wl[c], a0); a1 = fmaf(f, Wl[512 + c], a1);
        a2 = fmaf(f, Wl[1024 + c], a2); a3 = fmaf(f, Wl[1536 + c], a3);
    }
    for (int o = 16; o; o >>= 1) {
        a0 += __shfl_xor_sync(~0u, a0, o); a1 += __shfl_xor_sync(~0u, a1, o);
        a2 += __shfl_xor_sync(~0u, a2, o); a3 += __shfl_xor_sync(~0u, a3, o);
    }
    if (lane < 4) {
        float v = (lane == 0) ? a0 : (lane == 1) ? a1 : (lane == 2) ? a2 : a3;
        g_P[(size_t)(b * 256 + l) * 4 + lane] = v;
    }
}

// ---- K1: [32768 x 512] @ [512 x 256] -> projT (transposed store) ----
__global__ __launch_bounds__(256) void k1_gemm(const float* __restrict__ fea)
{
    __shared__ float As[16 * 128];
    __shared__ float Bs[16 * 128];
    const int m0 = blockIdx.y * 128, n0 = blockIdx.x * 128;
    const int tid = threadIdx.x, ty = tid >> 4, tx = tid & 15;
    float acc[8][8];
#pragma unroll
    for (int i = 0; i < 8; i++)
#pragma unroll
        for (int j = 0; j < 8; j++) acc[i][j] = 0.0f;

    for (int k0 = 0; k0 < 512; k0 += 16) {
#pragma unroll
        for (int s = 0; s < 2; s++) {
            int idx = tid + s * 256;
            int row = idx >> 2, c4 = idx & 3;
            float4 v = *(const float4*)(fea + (size_t)(m0 + row) * 512 + k0 + c4 * 4);
            As[(c4 * 4 + 0) * 128 + row] = v.x; As[(c4 * 4 + 1) * 128 + row] = v.y;
            As[(c4 * 4 + 2) * 128 + row] = v.z; As[(c4 * 4 + 3) * 128 + row] = v.w;
        }
#pragma unroll
        for (int s = 0; s < 2; s++) {
            int idx = tid + s * 256;
            int kk = idx >> 5, n4 = idx & 31;
            *(float4*)(Bs + kk * 128 + n4 * 4) =
                *(const float4*)(g_Wcat1 + (size_t)(k0 + kk) * 256 + n0 + n4 * 4);
        }
        __syncthreads();
#pragma unroll
        for (int kk = 0; kk < 16; kk++) {
            float4 a0 = *(float4*)(As + kk * 128 + ty * 8);
            float4 a1 = *(float4*)(As + kk * 128 + ty * 8 + 4);
            float4 b0 = *(float4*)(Bs + kk * 128 + tx * 8);
            float4 b1 = *(float4*)(Bs + kk * 128 + tx * 8 + 4);
            float av[8] = {a0.x, a0.y, a0.z, a0.w, a1.x, a1.y, a1.z, a1.w};
            float bv[8] = {b0.x, b0.y, b0.z, b0.w, b1.x, b1.y, b1.z, b1.w};
#pragma unroll
            for (int i = 0; i < 8; i++)
#pragma unroll
                for (int j = 0; j < 8; j++) acc[i][j] = fmaf(av[i], bv[j], acc[i][j]);
        }
        __syncthreads();
    }
    const int b = m0 >> 8, l0 = m0 & 255;
#pragma unroll
    for (int i = 0; i < 8; i++)
#pragma unroll
        for (int j = 0; j < 8; j++)
            g_projT[((size_t)b * 256 + n0 + tx * 8 + j) * 256 + l0 + ty * 8 + i] = acc[i][j];
}

// ---- K2: 501-step recurrence, 2 batch rows per CTA ----
__global__ __launch_bounds__(1024, 1) void k2_loop(
    const float* __restrict__ fea,
    const float* __restrict__ b_h2h, const float* __restrict__ b_ih,
    const float* __restrict__ b_hh,  const float* __restrict__ w_score,
    const float* __restrict__ b_gen, float* __restrict__ probs_out)
{
    const int b0 = blockIdx.x * 2, tid = threadIdx.x;
    __shared__ __align__(16) float2 h2[256];                 // interleaved rows
    __shared__ __align__(16) float q_s[512], gh_s[1536], gi_s[1536];
    __shared__ __align__(16) float e_s[512], ctx_s[1024];
    __shared__ __align__(16) float scr[2048];
    __shared__ float ws_s[256], bh2h_s[256], bih_s[768], bhh_s[768], bgen_s[32];
    __shared__ int elem_sh[2];

    if (tid < 256) { h2[tid] = make_float2(0.f, 0.f); ws_s[tid] = w_score[tid]; bh2h_s[tid] = b_h2h[tid]; }
    if (tid < 768) { bih_s[tid] = b_ih[tid]; bhh_s[tid] = b_hh[tid]; }
    if (tid < 32)  bgen_s[tid] = (tid < 30) ? b_gen[tid] : 0.0f;
    if (tid < 2)   elem_sh[tid] = 0;
    __syncthreads();

    const float* proj0 = g_projT + (size_t)b0 * 65536;

    for (int t = 0; t < TT; t++) {
        // ---- A: [q|gh] = Wcomb @ h for both rows; split-j halves, float2 over outputs
        {
            const int hf = tid >> 9, p = tid & 511, o0 = 2 * p;
            const float* w = g_WcombT + (size_t)(hf * 128) * 1024 + o0;
            float a00 = 0, a10 = 0, a01 = 0, a11 = 0;
#pragma unroll 8
            for (int j = 0; j < 128; j++) {
                float2 wv = *(const float2*)(w + j * 1024);
                float2 hh = h2[hf * 128 + j];
                a00 = fmaf(wv.x, hh.x, a00); a10 = fmaf(wv.x, hh.y, a10);
                a01 = fmaf(wv.y, hh.x, a01); a11 = fmaf(wv.y, hh.y, a11);
            }
            if (hf) *(float4*)(scr + 4 * p) = make_float4(a00, a10, a01, a11);
            __syncthreads();
            if (!hf) {
                float4 f = *(float4*)(scr + 4 * p);
                a00 += f.x; a10 += f.y; a01 += f.z; a11 += f.w;
                if (o0 < 256) {
                    q_s[o0] = a00 + bh2h_s[o0];         q_s[256 + o0] = a10 + bh2h_s[o0];
                    q_s[o0 + 1] = a01 + bh2h_s[o0 + 1]; q_s[256 + o0 + 1] = a11 + bh2h_s[o0 + 1];
                } else {
                    int k = o0 - 256;
                    gh_s[k] = a00 + bhh_s[k];           gh_s[768 + k] = a10 + bhh_s[k];
                    gh_s[k + 1] = a01 + bhh_s[k + 1];   gh_s[768 + k + 1] = a11 + bhh_s[k + 1];
                }
            }
            __syncthreads();
        }
        // ---- B: e[r][l] = sum_h ws[h]*tanh(proj[r][h][l]+q[r][h]); (r, l-pair, h-quarter)
        {
            const int r = tid >> 9, rem = tid & 511, lp = rem & 127, c4 = rem >> 7;
            const float* pb = proj0 + (size_t)r * 65536 + (size_t)(c4 * 64) * 256 + 2 * lp;
            const float* qr = q_s + r * 256 + c4 * 64;
            const float* wr = ws_s + c4 * 64;
            float p0 = 0, p1 = 0;
#pragma unroll 8
            for (int hh = 0; hh < 64; hh++) {
                float2 pr = *(const float2*)(pb + hh * 256);
                float qv = qr[hh], wv = wr[hh];
                p0 = fmaf(wv, tanhfast(pr.x + qv), p0);
                p1 = fmaf(wv, tanhfast(pr.y + qv), p1);
            }
            *(float2*)(scr + 2 * tid) = make_float2(p0, p1);
        }
        __syncthreads();
        if (tid < 512) {
            const int r = tid >> 8, l = tid & 255, lp = l >> 1, sub = l & 1;
            float e = 0;
#pragma unroll
            for (int c4 = 0; c4 < 4; c4++) {
                float2 v = *(const float2*)(scr + 2 * (r * 512 + c4 * 128 + lp));
                e += sub ? v.y : v.x;
            }
            e_s[tid] = e;
        }
        __syncthreads();
        // ---- softmax per row (warps 0-7 row0, 8-15 row1)
        if (tid < 512) {
            float v = e_s[tid];
            for (int o = 16; o; o >>= 1) v = fmaxf(v, __shfl_xor_sync(~0u, v, o));
            if ((tid & 31) == 0) scr[1920 + (tid >> 5)] = v;
        }
        __syncthreads();
        if (tid < 512) {
            const int r = tid >> 8;
            float mx = scr[1920 + r * 8];
#pragma unroll
            for (int w = 1; w < 8; w++) mx = fmaxf(mx, scr[1920 + r * 8 + w]);
            float a = __expf(e_s[tid] - mx);
            e_s[tid] = a;
            for (int o = 16; o; o >>= 1) a += __shfl_xor_sync(~0u, a, o);
            if ((tid & 31) == 0) scr[1952 + (tid >> 5)] = a;
        }
        __syncthreads();
        if (tid < 512) {
            const int r = tid >> 8;
            float s = scr[1952 + r * 8];
#pragma unroll
            for (int w = 1; w < 8; w++) s += scr[1952 + r * 8 + w];
            e_s[tid] *= (1.0f / s);
        }
        __syncthreads();
        // ---- ctx[r][c] = sum_l alpha[r][l]*fea[r][l][c]; (r, c-pair, l-half)
        {
            const int r = tid >> 9, rem = tid & 511, cp = rem & 255, lh = rem >> 8;
            const float* fp = fea + ((size_t)(b0 + r) * 256 + lh * 128) * 512 + 2 * cp;
            const float* al = e_s + r * 256 + lh * 128;
            float a0 = 0, a1 = 0;
#pragma unroll 8
            for (int l = 0; l < 128; l++) {
                float2 fv = *(const float2*)(fp + (size_t)l * 512);
                float av = al[l];
                a0 = fmaf(av, fv.x, a0); a1 = fmaf(av, fv.y, a1);
            }
            if (lh) *(float2*)(scr + 2 * (r * 256 + cp)) = make_float2(a0, a1);
            __syncthreads();
            if (!lh) {
                float2 f = *(float2*)(scr + 2 * (r * 256 + cp));
                ctx_s[r * 512 + 2 * cp] = a0 + f.x;
                ctx_s[r * 512 + 2 * cp + 1] = a1 + f.y;
            }
            __syncthreads();
        }
        // ---- C: gi[r][k] = W_ihc @ ctx[r] + b_ih + OH[elem_r]; (k-pair, c-half)
        {
            const bool act = tid < 768;
            const int snd = (tid >= 384 && tid < 768) ? 1 : 0;
            const int p = act ? (tid - snd * 384) : 0, k0 = 2 * p;
            float a00 = 0, a10 = 0, a01 = 0, a11 = 0;
            if (act) {
                const float* w = g_WihcT + (size_t)(snd * 256) * 768 + k0;
                const float* c0p = ctx_s + snd * 256;
                const float* c1p = ctx_s + 512 + snd * 256;
#pragma unroll 8
                for (int c = 0; c < 256; c++) {
                    float2 wv = *(const float2*)(w + (size_t)c * 768);
                    float cv0 = c0p[c], cv1 = c1p[c];
                    a00 = fmaf(wv.x, cv0, a00); a10 = fmaf(wv.x, cv1, a10);
                    a01 = fmaf(wv.y, cv0, a01); a11 = fmaf(wv.y, cv1, a11);
                }
                if (snd) *(float4*)(scr + 4 * p) = make_float4(a00, a10, a01, a11);
            }
            __syncthreads();
            if (act && !snd) {
                float4 f = *(float4*)(scr + 4 * p);
                const int e0 = elem_sh[0], e1 = elem_sh[1];
                gi_s[k0]           = a00 + f.x + bih_s[k0]     + g_OH[e0 * 768 + k0];
                gi_s[768 + k0]     = a10 + f.y + bih_s[k0]     + g_OH[e1 * 768 + k0];
                gi_s[k0 + 1]       = a01 + f.z + bih_s[k0 + 1] + g_OH[e0 * 768 + k0 + 1];
                gi_s[768 + k0 + 1] = a11 + f.w + bih_s[k0 + 1] + g_OH[e1 * 768 + k0 + 1];
            }
            __syncthreads();
        }
        // ---- D: GRU combine
        if (tid < 512) {
            const int r = tid >> 8, i = tid & 255;
            const float* gir = gi_s + r * 768;
            const float* ghr = gh_s + r * 768;
            float rg = sigm(gir[i] + ghr[i]);
            float z  = sigm(gir[256 + i] + ghr[256 + i]);
            float n  = tanhfast(gir[512 + i] + rg * ghr[512 + i]);
            float* hp = (float*)h2;
            float hprev = hp[2 * i + r];
            hp[2 * i + r] = (1.0f - z) * n + z * hprev;
        }
        __syncthreads();
        // ---- E: logits partials (tid<512) + hid4 partials (all threads)
        if (tid < 512) {
            const int r = tid >> 8, i = tid & 255, m = i & 31, j0 = (i >> 5) * 32;
            const float* wg = g_WgenT + j0 * 32 + m;
            const float* hp = (const float*)h2;
            float p2 = 0;
#pragma unroll 8
            for (int jj = 0; jj < 32; jj++) p2 = fmaf(wg[jj * 32], hp[2 * (j0 + jj) + r], p2);
            scr[tid] = p2;
        }
        {
            const int w = tid >> 5, lane = tid & 31;
            const int r = w >> 4, m = (w >> 2) & 3, qd = w & 3;
            const int j = qd * 32 + lane;
            const float* hp = (const float*)h2;
            float v = g_WlgHT[j * 4 + m] * hp[2 * j + r]
                    + g_WlgHT[(j + 128) * 4 + m] * hp[2 * (j + 128) + r];
            for (int o = 16; o; o >>= 1) v += __shfl_xor_sync(~0u, v, o);
            if (lane == 0) scr[1024 + w] = v;
        }
        __syncthreads();
        // ---- finalize: argmax+probs (warps 0,1), hid4 store (threads 64-71)
        if (tid < 64) {
            const int r = tid >> 5, m = tid & 31;
            float s = bgen_s[m];
#pragma unroll
            for (int g = 0; g < 8; g++) s += scr[r * 256 + m + g * 32];
            float v = (m < 30) ? s : -1e30f;
            float bv = v; int bi = m;
            for (int o = 16; o; o >>= 1) {
                float ov = __shfl_down_sync(~0u, bv, o);
                int   oi = __shfl_down_sync(~0u, bi, o);
                if (ov > bv || (ov == bv && oi < bi)) { bv = ov; bi = oi; }
            }
            bv = __shfl_sync(~0u, bv, 0); bi = __shfl_sync(~0u, bi, 0);
            float ex = (m < 30) ? __expf(v - bv) : 0.0f;
            float sm = ex;
            for (int o = 16; o; o >>= 1) sm += __shfl_xor_sync(~0u, sm, o);
            if (m < 30) probs_out[((size_t)(b0 + r) * TT + t) * 30 + m] = ex / sm;
            if (m == 0) elem_sh[r] = bi;
        } else if (tid < 72) {
            const int r2 = (tid - 64) >> 2, m2 = (tid - 64) & 3;
            float s = 0;
#pragma unroll
            for (int q = 0; q < 4; q++) s += scr[1024 + r2 * 16 + m2 * 4 + q];
            g_hid4[((size_t)(b0 + r2) * TT + t) * 4 + m2] = s;
        }
        __syncthreads();
    }
}

// ---- K3: loc_preds ----
__global__ __launch_bounds__(256) void k3_loc(
    const float* __restrict__ Wlt, const float* __restrict__ blt,
    const float* __restrict__ blg, float* __restrict__ loc_out)
{
    __shared__ float Ps[1024];
    const int b = blockIdx.y, tid = threadIdx.x, lane = tid & 31, w = tid >> 5;
    for (int i = tid; i < 1024; i += 256) Ps[i] = g_P[(size_t)b * 1024 + i];
    __syncthreads();
    int t = blockIdx.x * 8 + w;
    if (t >= TT) return;
    float a0 = 0, a1 = 0, a2 = 0, a3 = 0;
    const float* wp = Wlt + (size_t)t * 256;
    for (int i = 0; i < 8; i++) {
        int l = lane + 32 * i;
        float wv = wp[l];
        float4 p = *(float4*)(Ps + l * 4);
        a0 = fmaf(wv, p.x, a0); a1 = fmaf(wv, p.y, a1);
        a2 = fmaf(wv, p.z, a2); a3 = fmaf(wv, p.w, a3);
    }
    for (int o = 16; o; o >>= 1) {
        a0 += __shfl_xor_sync(~0u, a0, o); a1 += __shfl_xor_sync(~0u, a1, o);
        a2 += __shfl_xor_sync(~0u, a2, o); a3 += __shfl_xor_sync(~0u, a3, o);
    }
    if (lane < 4) {
        float v = (lane == 0) ? a0 : (lane == 1) ? a1 : (lane == 2) ? a2 : a3;
        v += blt[t] * g_S[lane] + blg[lane] + g_hid4[((size_t)b * TT + t) * 4 + lane];
        loc_out[((size_t)b * TT + t) * 4 + lane] = sigm(v);
    }
}

extern "C" void kernel_launch(void* const* d_in, const int* in_sizes, int n_in,
                              void* d_out, int out_size)
{
    const float* fea     = (const float*)d_in[0];
    const float* W_i2h   = (const float*)d_in[1];
    const float* W_h2h   = (const float*)d_in[2];
    const float* b_h2h   = (const float*)d_in[3];
    const float* w_score = (const float*)d_in[4];
    const float* W_ih    = (const float*)d_in[5];
    const float* W_hh    = (const float*)d_in[6];
    const float* b_ih    = (const float*)d_in[7];
    const float* b_hh    = (const float*)d_in[8];
    const float* W_gen   = (const float*)d_in[9];
    const float* b_gen   = (const float*)d_in[10];
    const float* Wlt     = (const float*)d_in[11];
    const float* blt     = (const float*)d_in[12];
    const float* W_lg    = (const float*)d_in[13];
    const float* blg     = (const float*)d_in[14];

    float* out = (float*)d_out;
    float* probs = out;
    float* loc   = out + (size_t)BN * TT * ENM;

    k0_prep<<<256, 256>>>(W_i2h, W_h2h, W_ih, W_hh, W_gen, W_lg);
    kP<<<dim3(32, 128), 256>>>(fea, W_lg);
    k1_gemm<<<dim3(2, 256), 256>>>(fea);
    k2_loop<<<64, 1024>>>(fea, b_h2h, b_ih, b_hh, w_score, b_gen, probs);
    k3_loc<<<dim3(63, 128), 256>>>(Wlt, blt, blg, loc);
}